// round 1
// baseline (speedup 1.0000x reference)
#include <cuda_runtime.h>
#include <math.h>

#define BSZ 2
#define SEQ 2048
#define DIM 1024
#define NH  16
#define HD  64
#define NTOK (BSZ*SEQ)            // 4096
#define NELEM ((size_t)NTOK*DIM)  // 4,194,304

// Scratch (allocation-free rule: use __device__ globals)
__device__ float g_Q[NELEM];
__device__ float g_K[NELEM];
__device__ float g_V[NELEM];
__device__ float g_M[NELEM];   // merged attention output [B,S,H*HD]

// ---------------------------------------------------------------------------
// SGEMM: C[M,N] = A[M,K] @ B[K,N], all row-major, fp32.
// 128x128 block tile, BK=8, 8x8 per thread, 256 threads.
// ---------------------------------------------------------------------------
__global__ void __launch_bounds__(256)
sgemm128(const float* __restrict__ A, const float* __restrict__ B,
         float* __restrict__ C, int M, int N, int K)
{
    __shared__ float As[8][128];   // A transposed: As[k][m]
    __shared__ float Bs[8][128];   // Bs[k][n]

    const int tid = threadIdx.x;
    const int cRow = blockIdx.y;
    const int cCol = blockIdx.x;

    const int threadRow = tid / 16;       // 0..15 -> m micro-tile
    const int threadCol = tid % 16;       // 0..15 -> n micro-tile

    const int aRow = tid / 2;             // 0..127
    const int aCol = (tid % 2) * 4;       // 0 or 4
    const int bRow = tid / 32;            // 0..7
    const int bCol = (tid % 32) * 4;      // 0..124

    const float* Ab = A + (size_t)cRow * 128 * K;
    const float* Bb = B + cCol * 128;

    float acc[8][8];
    #pragma unroll
    for (int i = 0; i < 8; i++)
        #pragma unroll
        for (int j = 0; j < 8; j++) acc[i][j] = 0.0f;

    for (int k0 = 0; k0 < K; k0 += 8) {
        float4 a = *(const float4*)(Ab + (size_t)aRow * K + k0 + aCol);
        As[aCol + 0][aRow] = a.x;
        As[aCol + 1][aRow] = a.y;
        As[aCol + 2][aRow] = a.z;
        As[aCol + 3][aRow] = a.w;
        *(float4*)(&Bs[bRow][bCol]) =
            *(const float4*)(Bb + (size_t)(k0 + bRow) * N + bCol);
        __syncthreads();

        #pragma unroll
        for (int kk = 0; kk < 8; kk++) {
            float regM[8], regN[8];
            *(float4*)(&regM[0]) = *(const float4*)(&As[kk][threadRow * 8 + 0]);
            *(float4*)(&regM[4]) = *(const float4*)(&As[kk][threadRow * 8 + 4]);
            *(float4*)(&regN[0]) = *(const float4*)(&Bs[kk][threadCol * 8 + 0]);
            *(float4*)(&regN[4]) = *(const float4*)(&Bs[kk][threadCol * 8 + 4]);
            #pragma unroll
            for (int i = 0; i < 8; i++)
                #pragma unroll
                for (int j = 0; j < 8; j++)
                    acc[i][j] += regM[i] * regN[j];
        }
        __syncthreads();
    }

    float* Cb = C + (size_t)cRow * 128 * N + cCol * 128;
    #pragma unroll
    for (int i = 0; i < 8; i++) {
        #pragma unroll
        for (int j = 0; j < 8; j += 4) {
            *(float4*)(Cb + (size_t)(threadRow * 8 + i) * N + threadCol * 8 + j) =
                make_float4(acc[i][j], acc[i][j+1], acc[i][j+2], acc[i][j+3]);
        }
    }
}

// ---------------------------------------------------------------------------
// Flash attention (fp32), causal-optional.
// Block: 256 threads handles a 64-row Q tile for one (b,h).
// Tiles of 64 K rows; online softmax; P staged through smem.
// Thread (ty,tx) [ty=tid/16, tx=tid%16] owns q-rows 4*ty+i, k/hd-cols tx+16*j.
// ---------------------------------------------------------------------------
#define BQ 64
#define BKT 64

__global__ void __launch_bounds__(256)
flash_attn(const float* __restrict__ Qg, const float* __restrict__ Kg,
           const float* __restrict__ Vg, float* __restrict__ merged,
           float* __restrict__ attn_out, int write_attn,
           const int* __restrict__ maskedp)
{
    extern __shared__ float sm[];
    float* Qs = sm;                 // [64][64]
    float* Ks = Qs + 64 * 64;       // [64][65]  (pad -> conflict-free reads)
    float* Vs = Ks + 64 * 65;       // [64][64]
    float* Ps = Vs + 64 * 64;       // [64][65]

    #define QS(r,c) Qs[(r)*64+(c)]
    #define KS(r,c) Ks[(r)*65+(c)]
    #define VS(r,c) Vs[(r)*64+(c)]
    #define PS(r,c) Ps[(r)*65+(c)]

    const int qt = blockIdx.x;     // q tile
    const int h  = blockIdx.y;
    const int b  = blockIdx.z;
    const int tid = threadIdx.x;
    const int ty = tid / 16;
    const int tx = tid % 16;
    const int q0 = qt * BQ;
    const int masked = maskedp[0];

    // Load Q tile (pre-scaled by 1/sqrt(hd) = 0.125)
    for (int idx = tid; idx < BQ * HD / 4; idx += 256) {
        int r  = idx / 16;
        int c4 = (idx % 16) * 4;
        float4 v = *(const float4*)(Qg + ((size_t)(b * SEQ + q0 + r) * DIM) + h * HD + c4);
        QS(r, c4 + 0) = v.x * 0.125f;
        QS(r, c4 + 1) = v.y * 0.125f;
        QS(r, c4 + 2) = v.z * 0.125f;
        QS(r, c4 + 3) = v.w * 0.125f;
    }

    float o[4][4];
    #pragma unroll
    for (int i = 0; i < 4; i++)
        #pragma unroll
        for (int j = 0; j < 4; j++) o[i][j] = 0.0f;
    float m_i[4], l_i[4];
    #pragma unroll
    for (int i = 0; i < 4; i++) { m_i[i] = -1e30f; l_i[i] = 0.0f; }

    const int ktmax = masked ? qt : (SEQ / BKT - 1);

    for (int kt = 0; kt <= ktmax; kt++) {
        const int k0 = kt * BKT;
        __syncthreads();   // previous PV / Q-load complete before overwriting tiles

        // Load K, V tiles
        for (int idx = tid; idx < BKT * HD / 4; idx += 256) {
            int r  = idx / 16;
            int c4 = (idx % 16) * 4;
            size_t base = ((size_t)(b * SEQ + k0 + r) * DIM) + h * HD + c4;
            float4 kv = *(const float4*)(Kg + base);
            KS(r, c4 + 0) = kv.x; KS(r, c4 + 1) = kv.y;
            KS(r, c4 + 2) = kv.z; KS(r, c4 + 3) = kv.w;
            float4 vv = *(const float4*)(Vg + base);
            *(float4*)(&VS(r, c4)) = vv;
        }
        __syncthreads();

        // Scores s[i][j] = (Q/8) . K   for q-row 4ty+i, k-col tx+16j
        float s[4][4];
        #pragma unroll
        for (int i = 0; i < 4; i++)
            #pragma unroll
            for (int j = 0; j < 4; j++) s[i][j] = 0.0f;

        #pragma unroll 8
        for (int d = 0; d < HD; d++) {
            float qv[4], kv[4];
            #pragma unroll
            for (int i = 0; i < 4; i++) qv[i] = QS(4 * ty + i, d);
            #pragma unroll
            for (int j = 0; j < 4; j++) kv[j] = KS(tx + 16 * j, d);
            #pragma unroll
            for (int i = 0; i < 4; i++)
                #pragma unroll
                for (int j = 0; j < 4; j++)
                    s[i][j] += qv[i] * kv[j];
        }

        if (masked && kt == qt) {
            #pragma unroll
            for (int i = 0; i < 4; i++) {
                int qg = q0 + 4 * ty + i;
                #pragma unroll
                for (int j = 0; j < 4; j++) {
                    int kg = k0 + tx + 16 * j;
                    if (kg > qg) s[i][j] = -1e30f;
                }
            }
        }

        // Online softmax (row reduce across the 16 tx lanes)
        #pragma unroll
        for (int i = 0; i < 4; i++) {
            float mt = s[i][0];
            #pragma unroll
            for (int j = 1; j < 4; j++) mt = fmaxf(mt, s[i][j]);
            #pragma unroll
            for (int off = 8; off >= 1; off >>= 1)
                mt = fmaxf(mt, __shfl_xor_sync(0xffffffffu, mt, off));
            float mnew = fmaxf(m_i[i], mt);
            float alpha = __expf(m_i[i] - mnew);
            m_i[i] = mnew;
            float rs = 0.0f;
            #pragma unroll
            for (int j = 0; j < 4; j++) {
                float p = __expf(s[i][j] - mnew);
                PS(4 * ty + i, tx + 16 * j) = p;
                rs += p;
            }
            #pragma unroll
            for (int off = 8; off >= 1; off >>= 1)
                rs += __shfl_xor_sync(0xffffffffu, rs, off);
            l_i[i] = l_i[i] * alpha + rs;
            #pragma unroll
            for (int j = 0; j < 4; j++) o[i][j] *= alpha;
        }
        __syncthreads();

        // PV: o[i][j] += P[qrow][k] * V[k][hdcol]
        #pragma unroll 8
        for (int k = 0; k < BKT; k++) {
            float pv[4], vv[4];
            #pragma unroll
            for (int i = 0; i < 4; i++) pv[i] = PS(4 * ty + i, k);
            #pragma unroll
            for (int j = 0; j < 4; j++) vv[j] = VS(k, tx + 16 * j);
            #pragma unroll
            for (int i = 0; i < 4; i++)
                #pragma unroll
                for (int j = 0; j < 4; j++)
                    o[i][j] += pv[i] * vv[j];
        }
    }

    // Normalize + write out
    #pragma unroll
    for (int i = 0; i < 4; i++) {
        float inv_l = 1.0f / l_i[i];
        int qg = q0 + 4 * ty + i;
        #pragma unroll
        for (int j = 0; j < 4; j++) {
            float val = o[i][j] * inv_l;
            int c = tx + 16 * j;
            merged[((size_t)(b * SEQ + qg) * DIM) + h * HD + c] = val;
            if (write_attn)
                attn_out[(((size_t)(b * NH + h) * SEQ + qg) * HD) + c] = val;
        }
    }
}

// ---------------------------------------------------------------------------
extern "C" void kernel_launch(void* const* d_in, const int* in_sizes, int n_in,
                              void* d_out, int out_size)
{
    const float* q  = (const float*)d_in[0];
    const float* k  = (const float*)d_in[1];
    const float* v  = (const float*)d_in[2];
    const float* Wq = (const float*)d_in[3];
    const float* Wk = (const float*)d_in[4];
    const float* Wv = (const float*)d_in[5];
    const float* Wo = (const float*)d_in[6];
    const int* masked = (const int*)d_in[7];
    float* out = (float*)d_out;

    float *pQ, *pK, *pV, *pM;
    cudaGetSymbolAddress((void**)&pQ, g_Q);
    cudaGetSymbolAddress((void**)&pK, g_K);
    cudaGetSymbolAddress((void**)&pV, g_V);
    cudaGetSymbolAddress((void**)&pM, g_M);

    dim3 gGemm(DIM / 128, NTOK / 128);   // (8, 32)

    // Projections
    sgemm128<<<gGemm, 256>>>(q, Wq, pQ, NTOK, DIM, DIM);
    sgemm128<<<gGemm, 256>>>(k, Wk, pK, NTOK, DIM, DIM);
    sgemm128<<<gGemm, 256>>>(v, Wv, pV, NTOK, DIM, DIM);

    // Attention
    int write_attn = (out_size >= (int)(2 * NELEM)) ? 1 : 0;
    float* attn_ptr = out + NELEM;
    size_t smem = (64 * 64 + 64 * 65 + 64 * 64 + 64 * 65) * sizeof(float);
    cudaFuncSetAttribute(flash_attn, cudaFuncAttributeMaxDynamicSharedMemorySize,
                         (int)smem);
    dim3 gAttn(SEQ / BQ, NH, BSZ);       // (32, 16, 2)
    flash_attn<<<gAttn, 256, smem>>>(pQ, pK, pV, pM, attn_ptr, write_attn, masked);

    // Output projection
    sgemm128<<<gGemm, 256>>>(pM, Wo, out, NTOK, DIM, DIM);
}

// round 2
// speedup vs baseline: 1.7336x; 1.7336x over previous
#include <cuda_runtime.h>
#include <math.h>

#define BSZ 2
#define SEQ 2048
#define DIM 1024
#define NH  16
#define HD  64
#define NTOK (BSZ*SEQ)            // 4096
#define NELEM ((size_t)NTOK*DIM)  // 4,194,304

// Scratch (allocation-free rule: use __device__ globals)
__device__ float g_Q[NELEM];
__device__ float g_K[NELEM];
__device__ float g_V[NELEM];
__device__ float g_M[NELEM];   // merged attention output [B,S,H*HD]

// ---------------------------------------------------------------------------
// TF32 tensor-core GEMM: C[M,N] = A[M,K] @ B[K,N], row-major fp32 in/out.
// 128x128 block tile, BK=32, 2-stage cp.async pipeline, 8 warps,
// warp tile 64x32 via mma.sync.m16n8k8.tf32.
// ---------------------------------------------------------------------------
#define GBM 128
#define GBN 128
#define GBK 32
#define ASTRIDE 36    // GBK + 4  (A-frag reads: bank = lane, conflict-free)
#define BSTRIDE 136   // GBN + 8  (B-frag reads: bank = 8k+g, conflict-free)
#define STAGE_FLOATS (GBM*ASTRIDE + GBK*BSTRIDE)   // 4608 + 4352 = 8960

__device__ __forceinline__ unsigned f2tf32(float f) {
    unsigned r;
    asm("cvt.rna.tf32.f32 %0, %1;" : "=r"(r) : "f"(f));
    return r;
}

__device__ __forceinline__ void cp_async16(unsigned smem_addr, const void* gptr) {
    asm volatile("cp.async.cg.shared.global [%0], [%1], 16;\n"
                 :: "r"(smem_addr), "l"(gptr));
}
__device__ __forceinline__ void cp_commit() {
    asm volatile("cp.async.commit_group;\n");
}
template <int N>
__device__ __forceinline__ void cp_wait() {
    asm volatile("cp.async.wait_group %0;\n" :: "n"(N));
}

__global__ void __launch_bounds__(256, 2)
gemm_tf32(const float* __restrict__ A, const float* __restrict__ B,
          float* __restrict__ C, int M, int N, int K)
{
    extern __shared__ float sm[];
    const int tid  = threadIdx.x;
    const int lane = tid & 31;
    const int warp = tid >> 5;
    const int wm   = warp >> 2;          // 0..1  (64 rows)
    const int wn   = warp & 3;           // 0..3  (32 cols)

    const int bRow = blockIdx.y;         // M tile
    const int bCol = blockIdx.x;         // N tile

    const float* Ab = A + (size_t)bRow * GBM * K;
    const float* Bb = B + (size_t)bCol * GBN;

    unsigned smem_base;
    asm("{ .reg .u64 t; cvta.to.shared.u64 t, %1; cvt.u32.u64 %0, t; }"
        : "=r"(smem_base) : "l"(sm));

    // per-stage smem offsets (in floats)
    //   As[s]: [GBM][ASTRIDE], Bs[s]: [GBK][BSTRIDE]
    const int aRowL = tid >> 3;          // 0..31, +32*it
    const int aColL = (tid & 7) * 4;
    const int bRowL = tid >> 5;          // 0..7, +8*it
    const int bColL = (tid & 31) * 4;

    float c[4][4][4];
    #pragma unroll
    for (int mt = 0; mt < 4; mt++)
        #pragma unroll
        for (int nt = 0; nt < 4; nt++)
            #pragma unroll
            for (int e = 0; e < 4; e++) c[mt][nt][e] = 0.0f;

    const int niter = K / GBK;

    // stage loader
    auto load_stage = [&](int iter, int buf) {
        const int k0 = iter * GBK;
        float* As = sm + buf * STAGE_FLOATS;
        float* Bs = As + GBM * ASTRIDE;
        unsigned aBase = smem_base + (unsigned)(buf * STAGE_FLOATS) * 4u;
        unsigned bBase = aBase + GBM * ASTRIDE * 4u;
        #pragma unroll
        for (int it = 0; it < 4; it++) {
            int r = aRowL + it * 32;
            cp_async16(aBase + (r * ASTRIDE + aColL) * 4u,
                       Ab + (size_t)r * K + k0 + aColL);
        }
        #pragma unroll
        for (int it = 0; it < 4; it++) {
            int r = bRowL + it * 8;
            cp_async16(bBase + (r * BSTRIDE + bColL) * 4u,
                       Bb + (size_t)(k0 + r) * N + bColL);
        }
        (void)As; (void)Bs;
    };

    load_stage(0, 0); cp_commit();
    load_stage(1, 1); cp_commit();

    const int g  = lane >> 2;            // groupID 0..7
    const int tg = lane & 3;             // thread-in-group 0..3

    for (int i = 0; i < niter; i++) {
        cp_wait<1>();
        __syncthreads();

        const int buf = i & 1;
        const float* As = sm + buf * STAGE_FLOATS;
        const float* Bs = As + GBM * ASTRIDE;

        #pragma unroll
        for (int kk = 0; kk < GBK / 8; kk++) {
            unsigned af[4][4], bf[4][2];
            const int c0 = kk * 8 + tg;
            #pragma unroll
            for (int mt = 0; mt < 4; mt++) {
                int r0 = wm * 64 + mt * 16 + g;
                af[mt][0] = f2tf32(As[r0       * ASTRIDE + c0]);
                af[mt][1] = f2tf32(As[(r0 + 8) * ASTRIDE + c0]);
                af[mt][2] = f2tf32(As[r0       * ASTRIDE + c0 + 4]);
                af[mt][3] = f2tf32(As[(r0 + 8) * ASTRIDE + c0 + 4]);
            }
            #pragma unroll
            for (int nt = 0; nt < 4; nt++) {
                int col = wn * 32 + nt * 8 + g;
                bf[nt][0] = f2tf32(Bs[c0       * BSTRIDE + col]);
                bf[nt][1] = f2tf32(Bs[(c0 + 4) * BSTRIDE + col]);
            }
            #pragma unroll
            for (int mt = 0; mt < 4; mt++)
                #pragma unroll
                for (int nt = 0; nt < 4; nt++) {
                    asm volatile(
                        "mma.sync.aligned.m16n8k8.row.col.f32.tf32.tf32.f32 "
                        "{%0,%1,%2,%3},{%4,%5,%6,%7},{%8,%9},{%0,%1,%2,%3};\n"
                        : "+f"(c[mt][nt][0]), "+f"(c[mt][nt][1]),
                          "+f"(c[mt][nt][2]), "+f"(c[mt][nt][3])
                        : "r"(af[mt][0]), "r"(af[mt][1]),
                          "r"(af[mt][2]), "r"(af[mt][3]),
                          "r"(bf[nt][0]), "r"(bf[nt][1]));
                }
        }
        __syncthreads();
        if (i + 2 < niter) load_stage(i + 2, buf);
        cp_commit();   // empty commit keeps the group count uniform
    }

    // Epilogue
    float* Cb = C + (size_t)bRow * GBM * N + bCol * GBN;
    #pragma unroll
    for (int mt = 0; mt < 4; mt++) {
        int r0 = wm * 64 + mt * 16 + g;
        #pragma unroll
        for (int nt = 0; nt < 4; nt++) {
            int col = wn * 32 + nt * 8 + 2 * tg;
            *(float2*)(Cb + (size_t)r0 * N + col) =
                make_float2(c[mt][nt][0], c[mt][nt][1]);
            *(float2*)(Cb + (size_t)(r0 + 8) * N + col) =
                make_float2(c[mt][nt][2], c[mt][nt][3]);
        }
    }
}

// ---------------------------------------------------------------------------
// Flash attention (fp32), causal-optional. (unchanged from R1)
// ---------------------------------------------------------------------------
#define BQ 64
#define BKT 64

__global__ void __launch_bounds__(256)
flash_attn(const float* __restrict__ Qg, const float* __restrict__ Kg,
           const float* __restrict__ Vg, float* __restrict__ merged,
           float* __restrict__ attn_out, int write_attn,
           const int* __restrict__ maskedp)
{
    extern __shared__ float smf[];
    float* Qs = smf;                // [64][64]
    float* Ks = Qs + 64 * 64;       // [64][65]
    float* Vs = Ks + 64 * 65;       // [64][64]
    float* Ps = Vs + 64 * 64;       // [64][65]

    #define QS(r,c) Qs[(r)*64+(c)]
    #define KS(r,c) Ks[(r)*65+(c)]
    #define VS(r,c) Vs[(r)*64+(c)]
    #define PS(r,c) Ps[(r)*65+(c)]

    const int qt = blockIdx.x;
    const int h  = blockIdx.y;
    const int b  = blockIdx.z;
    const int tid = threadIdx.x;
    const int ty = tid / 16;
    const int tx = tid % 16;
    const int q0 = qt * BQ;
    const int masked = maskedp[0];

    for (int idx = tid; idx < BQ * HD / 4; idx += 256) {
        int r  = idx / 16;
        int c4 = (idx % 16) * 4;
        float4 v = *(const float4*)(Qg + ((size_t)(b * SEQ + q0 + r) * DIM) + h * HD + c4);
        QS(r, c4 + 0) = v.x * 0.125f;
        QS(r, c4 + 1) = v.y * 0.125f;
        QS(r, c4 + 2) = v.z * 0.125f;
        QS(r, c4 + 3) = v.w * 0.125f;
    }

    float o[4][4];
    #pragma unroll
    for (int i = 0; i < 4; i++)
        #pragma unroll
        for (int j = 0; j < 4; j++) o[i][j] = 0.0f;
    float m_i[4], l_i[4];
    #pragma unroll
    for (int i = 0; i < 4; i++) { m_i[i] = -1e30f; l_i[i] = 0.0f; }

    const int ktmax = masked ? qt : (SEQ / BKT - 1);

    for (int kt = 0; kt <= ktmax; kt++) {
        const int k0 = kt * BKT;
        __syncthreads();

        for (int idx = tid; idx < BKT * HD / 4; idx += 256) {
            int r  = idx / 16;
            int c4 = (idx % 16) * 4;
            size_t base = ((size_t)(b * SEQ + k0 + r) * DIM) + h * HD + c4;
            float4 kv = *(const float4*)(Kg + base);
            KS(r, c4 + 0) = kv.x; KS(r, c4 + 1) = kv.y;
            KS(r, c4 + 2) = kv.z; KS(r, c4 + 3) = kv.w;
            float4 vv = *(const float4*)(Vg + base);
            *(float4*)(&VS(r, c4)) = vv;
        }
        __syncthreads();

        float s[4][4];
        #pragma unroll
        for (int i = 0; i < 4; i++)
            #pragma unroll
            for (int j = 0; j < 4; j++) s[i][j] = 0.0f;

        #pragma unroll 8
        for (int d = 0; d < HD; d++) {
            float qv[4], kv[4];
            #pragma unroll
            for (int i = 0; i < 4; i++) qv[i] = QS(4 * ty + i, d);
            #pragma unroll
            for (int j = 0; j < 4; j++) kv[j] = KS(tx + 16 * j, d);
            #pragma unroll
            for (int i = 0; i < 4; i++)
                #pragma unroll
                for (int j = 0; j < 4; j++)
                    s[i][j] += qv[i] * kv[j];
        }

        if (masked && kt == qt) {
            #pragma unroll
            for (int i = 0; i < 4; i++) {
                int qg = q0 + 4 * ty + i;
                #pragma unroll
                for (int j = 0; j < 4; j++) {
                    int kg = k0 + tx + 16 * j;
                    if (kg > qg) s[i][j] = -1e30f;
                }
            }
        }

        #pragma unroll
        for (int i = 0; i < 4; i++) {
            float mt = s[i][0];
            #pragma unroll
            for (int j = 1; j < 4; j++) mt = fmaxf(mt, s[i][j]);
            #pragma unroll
            for (int off = 8; off >= 1; off >>= 1)
                mt = fmaxf(mt, __shfl_xor_sync(0xffffffffu, mt, off));
            float mnew = fmaxf(m_i[i], mt);
            float alpha = __expf(m_i[i] - mnew);
            m_i[i] = mnew;
            float rs = 0.0f;
            #pragma unroll
            for (int j = 0; j < 4; j++) {
                float p = __expf(s[i][j] - mnew);
                PS(4 * ty + i, tx + 16 * j) = p;
                rs += p;
            }
            #pragma unroll
            for (int off = 8; off >= 1; off >>= 1)
                rs += __shfl_xor_sync(0xffffffffu, rs, off);
            l_i[i] = l_i[i] * alpha + rs;
            #pragma unroll
            for (int j = 0; j < 4; j++) o[i][j] *= alpha;
        }
        __syncthreads();

        #pragma unroll 8
        for (int k = 0; k < BKT; k++) {
            float pv[4], vv[4];
            #pragma unroll
            for (int i = 0; i < 4; i++) pv[i] = PS(4 * ty + i, k);
            #pragma unroll
            for (int j = 0; j < 4; j++) vv[j] = VS(k, tx + 16 * j);
            #pragma unroll
            for (int i = 0; i < 4; i++)
                #pragma unroll
                for (int j = 0; j < 4; j++)
                    o[i][j] += pv[i] * vv[j];
        }
    }

    #pragma unroll
    for (int i = 0; i < 4; i++) {
        float inv_l = 1.0f / l_i[i];
        int qg = q0 + 4 * ty + i;
        #pragma unroll
        for (int j = 0; j < 4; j++) {
            float val = o[i][j] * inv_l;
            int c = tx + 16 * j;
            merged[((size_t)(b * SEQ + qg) * DIM) + h * HD + c] = val;
            if (write_attn)
                attn_out[(((size_t)(b * NH + h) * SEQ + qg) * HD) + c] = val;
        }
    }
}

// ---------------------------------------------------------------------------
extern "C" void kernel_launch(void* const* d_in, const int* in_sizes, int n_in,
                              void* d_out, int out_size)
{
    const float* q  = (const float*)d_in[0];
    const float* k  = (const float*)d_in[1];
    const float* v  = (const float*)d_in[2];
    const float* Wq = (const float*)d_in[3];
    const float* Wk = (const float*)d_in[4];
    const float* Wv = (const float*)d_in[5];
    const float* Wo = (const float*)d_in[6];
    const int* masked = (const int*)d_in[7];
    float* out = (float*)d_out;

    float *pQ, *pK, *pV, *pM;
    cudaGetSymbolAddress((void**)&pQ, g_Q);
    cudaGetSymbolAddress((void**)&pK, g_K);
    cudaGetSymbolAddress((void**)&pV, g_V);
    cudaGetSymbolAddress((void**)&pM, g_M);

    dim3 gGemm(DIM / GBN, NTOK / GBM);   // (8, 32)
    size_t gemm_smem = 2 * STAGE_FLOATS * sizeof(float);   // 71,680 B
    cudaFuncSetAttribute(gemm_tf32, cudaFuncAttributeMaxDynamicSharedMemorySize,
                         (int)gemm_smem);

    // Projections (tf32 tensor cores)
    gemm_tf32<<<gGemm, 256, gemm_smem>>>(q, Wq, pQ, NTOK, DIM, DIM);
    gemm_tf32<<<gGemm, 256, gemm_smem>>>(k, Wk, pK, NTOK, DIM, DIM);
    gemm_tf32<<<gGemm, 256, gemm_smem>>>(v, Wv, pV, NTOK, DIM, DIM);

    // Attention
    int write_attn = (out_size >= (int)(2 * NELEM)) ? 1 : 0;
    float* attn_ptr = out + NELEM;
    size_t smem = (64 * 64 + 64 * 65 + 64 * 64 + 64 * 65) * sizeof(float);
    cudaFuncSetAttribute(flash_attn, cudaFuncAttributeMaxDynamicSharedMemorySize,
                         (int)smem);
    dim3 gAttn(SEQ / BQ, NH, BSZ);       // (32, 16, 2)
    flash_attn<<<gAttn, 256, smem>>>(pQ, pK, pV, pM, attn_ptr, write_attn, masked);

    // Output projection (tf32 tensor cores)
    gemm_tf32<<<gGemm, 256, gemm_smem>>>(pM, Wo, out, NTOK, DIM, DIM);
}

// round 3
// speedup vs baseline: 3.0219x; 1.7432x over previous
#include <cuda_runtime.h>
#include <cuda_bf16.h>
#include <math.h>

#define BSZ 2
#define SEQ 2048
#define DIM 1024
#define NH  16
#define HD  64
#define NTOK (BSZ*SEQ)            // 4096
#define NELEM ((size_t)NTOK*DIM)  // 4,194,304

// Scratch (allocation-free rule: __device__ globals)
__device__ float g_M[NELEM];               // merged attention output [B,S,H*HD]
__device__ __nv_bfloat16 g_Qh[NELEM], g_Ql[NELEM];
__device__ __nv_bfloat16 g_Kh[NELEM], g_Kl[NELEM];
__device__ __nv_bfloat16 g_Vh[NELEM], g_Vl[NELEM];

// ---------------------------------------------------------------------------
// small PTX helpers
// ---------------------------------------------------------------------------
__device__ __forceinline__ unsigned f2tf32(float f) {
    unsigned r;
    asm("cvt.rna.tf32.f32 %0, %1;" : "=r"(r) : "f"(f));
    return r;
}
__device__ __forceinline__ unsigned packbf2(float hi, float lo) {
    unsigned d;
    asm("cvt.rn.bf16x2.f32 %0, %1, %2;" : "=r"(d) : "f"(hi), "f"(lo));
    return d;
}
__device__ __forceinline__ void cp_async16(unsigned smem_addr, const void* gptr) {
    asm volatile("cp.async.cg.shared.global [%0], [%1], 16;\n"
                 :: "r"(smem_addr), "l"(gptr));
}
__device__ __forceinline__ void cp_commit() {
    asm volatile("cp.async.commit_group;\n");
}
template <int N>
__device__ __forceinline__ void cp_wait() {
    asm volatile("cp.async.wait_group %0;\n" :: "n"(N));
}
__device__ __forceinline__ void ldsm_x4(unsigned* r, unsigned addr) {
    asm volatile("ldmatrix.sync.aligned.m8n8.x4.shared.b16 {%0,%1,%2,%3}, [%4];"
                 : "=r"(r[0]), "=r"(r[1]), "=r"(r[2]), "=r"(r[3]) : "r"(addr));
}
__device__ __forceinline__ void ldsm_x4_t(unsigned* r, unsigned addr) {
    asm volatile("ldmatrix.sync.aligned.m8n8.x4.trans.shared.b16 {%0,%1,%2,%3}, [%4];"
                 : "=r"(r[0]), "=r"(r[1]), "=r"(r[2]), "=r"(r[3]) : "r"(addr));
}
__device__ __forceinline__ void mma_bf16(float* c, const unsigned* a,
                                         unsigned b0, unsigned b1) {
    asm volatile(
        "mma.sync.aligned.m16n8k16.row.col.f32.bf16.bf16.f32 "
        "{%0,%1,%2,%3},{%4,%5,%6,%7},{%8,%9},{%0,%1,%2,%3};"
        : "+f"(c[0]), "+f"(c[1]), "+f"(c[2]), "+f"(c[3])
        : "r"(a[0]), "r"(a[1]), "r"(a[2]), "r"(a[3]), "r"(b0), "r"(b1));
}

// ---------------------------------------------------------------------------
// TF32 tensor-core GEMM (same mainloop as R2); epilogue optionally emits
// bf16 hi/lo planes (for Q/K/V) instead of fp32.
// ---------------------------------------------------------------------------
#define GBM 128
#define GBN 128
#define GBK 32
#define ASTRIDE 36
#define BSTRIDE 136
#define STAGE_FLOATS (GBM*ASTRIDE + GBK*BSTRIDE)

__global__ void __launch_bounds__(256, 2)
gemm_tf32(const float* __restrict__ A, const float* __restrict__ B,
          float* __restrict__ Cf,
          __nv_bfloat16* __restrict__ Ch, __nv_bfloat16* __restrict__ Cl,
          float scale, int M, int N, int K)
{
    extern __shared__ float sm[];
    const int tid  = threadIdx.x;
    const int lane = tid & 31;
    const int warp = tid >> 5;
    const int wm   = warp >> 2;
    const int wn   = warp & 3;

    const int bRow = blockIdx.y;
    const int bCol = blockIdx.x;

    const float* Ab = A + (size_t)bRow * GBM * K;
    const float* Bb = B + (size_t)bCol * GBN;

    unsigned smem_base;
    asm("{ .reg .u64 t; cvta.to.shared.u64 t, %1; cvt.u32.u64 %0, t; }"
        : "=r"(smem_base) : "l"(sm));

    const int aRowL = tid >> 3;
    const int aColL = (tid & 7) * 4;
    const int bRowL = tid >> 5;
    const int bColL = (tid & 31) * 4;

    float c[4][4][4];
    #pragma unroll
    for (int mt = 0; mt < 4; mt++)
        #pragma unroll
        for (int nt = 0; nt < 4; nt++)
            #pragma unroll
            for (int e = 0; e < 4; e++) c[mt][nt][e] = 0.0f;

    const int niter = K / GBK;

    auto load_stage = [&](int iter, int buf) {
        const int k0 = iter * GBK;
        unsigned aBase = smem_base + (unsigned)(buf * STAGE_FLOATS) * 4u;
        unsigned bBase = aBase + GBM * ASTRIDE * 4u;
        #pragma unroll
        for (int it = 0; it < 4; it++) {
            int r = aRowL + it * 32;
            cp_async16(aBase + (r * ASTRIDE + aColL) * 4u,
                       Ab + (size_t)r * K + k0 + aColL);
        }
        #pragma unroll
        for (int it = 0; it < 4; it++) {
            int r = bRowL + it * 8;
            cp_async16(bBase + (r * BSTRIDE + bColL) * 4u,
                       Bb + (size_t)(k0 + r) * N + bColL);
        }
    };

    load_stage(0, 0); cp_commit();
    load_stage(1, 1); cp_commit();

    const int g  = lane >> 2;
    const int tg = lane & 3;

    for (int i = 0; i < niter; i++) {
        cp_wait<1>();
        __syncthreads();

        const int buf = i & 1;
        const float* As = sm + buf * STAGE_FLOATS;
        const float* Bs = As + GBM * ASTRIDE;

        #pragma unroll
        for (int kk = 0; kk < GBK / 8; kk++) {
            unsigned af[4][4], bf[4][2];
            const int c0 = kk * 8 + tg;
            #pragma unroll
            for (int mt = 0; mt < 4; mt++) {
                int r0 = wm * 64 + mt * 16 + g;
                af[mt][0] = f2tf32(As[r0       * ASTRIDE + c0]);
                af[mt][1] = f2tf32(As[(r0 + 8) * ASTRIDE + c0]);
                af[mt][2] = f2tf32(As[r0       * ASTRIDE + c0 + 4]);
                af[mt][3] = f2tf32(As[(r0 + 8) * ASTRIDE + c0 + 4]);
            }
            #pragma unroll
            for (int nt = 0; nt < 4; nt++) {
                int col = wn * 32 + nt * 8 + g;
                bf[nt][0] = f2tf32(Bs[c0       * BSTRIDE + col]);
                bf[nt][1] = f2tf32(Bs[(c0 + 4) * BSTRIDE + col]);
            }
            #pragma unroll
            for (int mt = 0; mt < 4; mt++)
                #pragma unroll
                for (int nt = 0; nt < 4; nt++) {
                    asm volatile(
                        "mma.sync.aligned.m16n8k8.row.col.f32.tf32.tf32.f32 "
                        "{%0,%1,%2,%3},{%4,%5,%6,%7},{%8,%9},{%0,%1,%2,%3};\n"
                        : "+f"(c[mt][nt][0]), "+f"(c[mt][nt][1]),
                          "+f"(c[mt][nt][2]), "+f"(c[mt][nt][3])
                        : "r"(af[mt][0]), "r"(af[mt][1]),
                          "r"(af[mt][2]), "r"(af[mt][3]),
                          "r"(bf[nt][0]), "r"(bf[nt][1]));
                }
        }
        __syncthreads();
        if (i + 2 < niter) load_stage(i + 2, buf);
        cp_commit();
    }

    // Epilogue
    if (Ch) {
        // bf16 hi/lo planes, scaled
        #pragma unroll
        for (int mt = 0; mt < 4; mt++) {
            int r0 = bRow * GBM + wm * 64 + mt * 16 + g;
            #pragma unroll
            for (int nt = 0; nt < 4; nt++) {
                int col = bCol * GBN + wn * 32 + nt * 8 + 2 * tg;
                #pragma unroll
                for (int half = 0; half < 2; half++) {
                    size_t off = (size_t)(r0 + 8 * half) * N + col;
                    float y0 = c[mt][nt][2 * half + 0] * scale;
                    float y1 = c[mt][nt][2 * half + 1] * scale;
                    unsigned hi = packbf2(y1, y0);
                    float h0 = __uint_as_float(hi << 16);
                    float h1 = __uint_as_float(hi & 0xffff0000u);
                    unsigned lo = packbf2(y1 - h1, y0 - h0);
                    *(unsigned*)((__nv_bfloat16*)Ch + off) = hi;
                    *(unsigned*)((__nv_bfloat16*)Cl + off) = lo;
                }
            }
        }
    } else {
        float* Cb = Cf + (size_t)bRow * GBM * N + bCol * GBN;
        #pragma unroll
        for (int mt = 0; mt < 4; mt++) {
            int r0 = wm * 64 + mt * 16 + g;
            #pragma unroll
            for (int nt = 0; nt < 4; nt++) {
                int col = wn * 32 + nt * 8 + 2 * tg;
                *(float2*)(Cb + (size_t)r0 * N + col) =
                    make_float2(c[mt][nt][0], c[mt][nt][1]);
                *(float2*)(Cb + (size_t)(r0 + 8) * N + col) =
                    make_float2(c[mt][nt][2], c[mt][nt][3]);
            }
        }
    }
}

// ---------------------------------------------------------------------------
// Flash attention with bf16 tensor cores, 3-term hi/lo split (fp32-accurate).
// Block = 128 q-rows of one (b,h); 8 warps, each owns 16 q-rows.
// K-tiles of 64 columns. P never leaves registers (C-frag -> A-frag remap).
// ---------------------------------------------------------------------------
#define RS 72                         // smem row stride in bf16 (conflict-free)
#define SQH 0
#define SQL (128*RS)                  // 9216
#define SKH (2*128*RS)                // 18432
#define SKL (SKH + 64*RS)
#define SVH (SKL + 64*RS)
#define SVL (SVH + 64*RS)
#define SB_TOTAL (SVL + 64*RS)        // 36864 bf16 = 73728 B

__global__ void __launch_bounds__(256, 1)
flash_bf16(const __nv_bfloat16* __restrict__ Qh, const __nv_bfloat16* __restrict__ Ql,
           const __nv_bfloat16* __restrict__ Kh, const __nv_bfloat16* __restrict__ Kl,
           const __nv_bfloat16* __restrict__ Vh, const __nv_bfloat16* __restrict__ Vl,
           float* __restrict__ merged, float* __restrict__ attn_out,
           int write_attn, const int* __restrict__ maskedp)
{
    extern __shared__ __nv_bfloat16 sb[];
    const int qt  = gridDim.x - 1 - blockIdx.x;   // heavy (late-diag) blocks first
    const int h   = blockIdx.y;
    const int b   = blockIdx.z;
    const int tid = threadIdx.x;
    const int lane = tid & 31;
    const int w   = tid >> 5;
    const int q0  = qt * 128;
    const int masked = maskedp[0];

    unsigned sbase;
    asm("{ .reg .u64 t; cvta.to.shared.u64 t, %1; cvt.u32.u64 %0, t; }"
        : "=r"(sbase) : "l"(sb));

    // ---- load Q tile (128 x 64, both planes) ----
    for (int i = tid; i < 1024; i += 256) {
        int r = i >> 3, c8 = (i & 7) << 3;
        size_t gidx = ((size_t)(b * SEQ + q0 + r) * DIM) + h * HD + c8;
        *(uint4*)(sb + SQH + r * RS + c8) = *(const uint4*)(Qh + gidx);
        *(uint4*)(sb + SQL + r * RS + c8) = *(const uint4*)(Ql + gidx);
    }
    __syncthreads();

    // ---- hoist Q A-frags: [plane][dstep][4regs] ----
    unsigned qf[2][4][4];
    {
        int row  = 16 * w + (lane & 15);
        int coct = (lane >> 4) << 3;
        #pragma unroll
        for (int p = 0; p < 2; p++)
            #pragma unroll
            for (int d = 0; d < 4; d++) {
                unsigned addr = sbase +
                    ((p ? SQL : SQH) + row * RS + d * 16 + coct) * 2;
                ldsm_x4(qf[p][d], addr);
            }
    }

    float o[8][4];
    #pragma unroll
    for (int j = 0; j < 8; j++)
        #pragma unroll
        for (int e = 0; e < 4; e++) o[j][e] = 0.0f;
    float m0 = -1e30f, m1 = -1e30f, l0 = 0.0f, l1 = 0.0f;

    const int r_lo = q0 + 16 * w + (lane >> 2);
    const int r_hi = r_lo + 8;
    const int ktmax = masked ? (2 * qt + 1) : (SEQ / 64 - 1);

    for (int kt = 0; kt <= ktmax; kt++) {
        __syncthreads();
        // cooperative K/V tile load (64 x 64, 4 planes)
        for (int i = tid; i < 512; i += 256) {
            int r = i >> 3, c8 = (i & 7) << 3;
            size_t gidx = ((size_t)(b * SEQ + kt * 64 + r) * DIM) + h * HD + c8;
            *(uint4*)(sb + SKH + r * RS + c8) = *(const uint4*)(Kh + gidx);
            *(uint4*)(sb + SKL + r * RS + c8) = *(const uint4*)(Kl + gidx);
            *(uint4*)(sb + SVH + r * RS + c8) = *(const uint4*)(Vh + gidx);
            *(uint4*)(sb + SVL + r * RS + c8) = *(const uint4*)(Vl + gidx);
        }
        __syncthreads();

        const int k0 = kt * 64;
        if (masked && k0 > q0 + 16 * w + 15) continue;  // warp fully masked

        // ---- QK^T: s[8 ntiles][4] ----
        float s[8][4];
        #pragma unroll
        for (int j = 0; j < 8; j++)
            #pragma unroll
            for (int e = 0; e < 4; e++) s[j][e] = 0.0f;

        #pragma unroll
        for (int j = 0; j < 8; j++) {
            unsigned kbh[8], kbl[8];
            int krow = 8 * j + (lane & 7);
            int dct  = (lane >> 3) << 3;
            ldsm_x4(&kbh[0], sbase + (SKH + krow * RS + dct) * 2);
            ldsm_x4(&kbh[4], sbase + (SKH + krow * RS + 32 + dct) * 2);
            ldsm_x4(&kbl[0], sbase + (SKL + krow * RS + dct) * 2);
            ldsm_x4(&kbl[4], sbase + (SKL + krow * RS + 32 + dct) * 2);
            #pragma unroll
            for (int d = 0; d < 4; d++) {
                mma_bf16(s[j], qf[0][d], kbh[2*d], kbh[2*d+1]);  // hi*hi
                mma_bf16(s[j], qf[0][d], kbl[2*d], kbl[2*d+1]);  // hi*lo
                mma_bf16(s[j], qf[1][d], kbh[2*d], kbh[2*d+1]);  // lo*hi
            }
        }

        // ---- causal mask (diagonal band only) ----
        if (masked && k0 + 63 > r_lo) {
            #pragma unroll
            for (int j = 0; j < 8; j++) {
                int cc = k0 + 8 * j + 2 * (lane & 3);
                if (cc     > r_lo) s[j][0] = -1e30f;
                if (cc + 1 > r_lo) s[j][1] = -1e30f;
                if (cc     > r_hi) s[j][2] = -1e30f;
                if (cc + 1 > r_hi) s[j][3] = -1e30f;
            }
        }

        // ---- online softmax ----
        float mt0 = -1e30f, mt1 = -1e30f;
        #pragma unroll
        for (int j = 0; j < 8; j++) {
            mt0 = fmaxf(mt0, fmaxf(s[j][0], s[j][1]));
            mt1 = fmaxf(mt1, fmaxf(s[j][2], s[j][3]));
        }
        mt0 = fmaxf(mt0, __shfl_xor_sync(0xffffffffu, mt0, 1));
        mt0 = fmaxf(mt0, __shfl_xor_sync(0xffffffffu, mt0, 2));
        mt1 = fmaxf(mt1, __shfl_xor_sync(0xffffffffu, mt1, 1));
        mt1 = fmaxf(mt1, __shfl_xor_sync(0xffffffffu, mt1, 2));
        float mn0 = fmaxf(m0, mt0), mn1 = fmaxf(m1, mt1);
        float a0 = __expf(m0 - mn0), a1 = __expf(m1 - mn1);
        m0 = mn0; m1 = mn1;

        float rs0 = 0.0f, rs1 = 0.0f;
        unsigned pah[4][4], pal[4][4];
        #pragma unroll
        for (int j = 0; j < 8; j++) {
            float p0 = __expf(s[j][0] - mn0);
            float p1 = __expf(s[j][1] - mn0);
            float p2 = __expf(s[j][2] - mn1);
            float p3 = __expf(s[j][3] - mn1);
            rs0 += p0 + p1; rs1 += p2 + p3;
            unsigned h01 = packbf2(p1, p0);
            unsigned h23 = packbf2(p3, p2);
            float q0f = __uint_as_float(h01 << 16);
            float q1f = __uint_as_float(h01 & 0xffff0000u);
            float q2f = __uint_as_float(h23 << 16);
            float q3f = __uint_as_float(h23 & 0xffff0000u);
            unsigned lo01 = packbf2(p1 - q1f, p0 - q0f);
            unsigned lo23 = packbf2(p3 - q3f, p2 - q2f);
            int t = j >> 1, half = j & 1;
            pah[t][2 * half + 0] = h01;
            pah[t][2 * half + 1] = h23;
            pal[t][2 * half + 0] = lo01;
            pal[t][2 * half + 1] = lo23;
        }
        rs0 += __shfl_xor_sync(0xffffffffu, rs0, 1);
        rs0 += __shfl_xor_sync(0xffffffffu, rs0, 2);
        rs1 += __shfl_xor_sync(0xffffffffu, rs1, 1);
        rs1 += __shfl_xor_sync(0xffffffffu, rs1, 2);
        l0 = l0 * a0 + rs0;
        l1 = l1 * a1 + rs1;
        #pragma unroll
        for (int j = 0; j < 8; j++) {
            o[j][0] *= a0; o[j][1] *= a0;
            o[j][2] *= a1; o[j][3] *= a1;
        }

        // ---- PV ----
        #pragma unroll
        for (int jn = 0; jn < 8; jn++) {
            unsigned vbh[8], vbl[8];
            ldsm_x4_t(&vbh[0], sbase + (SVH + lane * RS + 8 * jn) * 2);
            ldsm_x4_t(&vbh[4], sbase + (SVH + (32 + lane) * RS + 8 * jn) * 2);
            ldsm_x4_t(&vbl[0], sbase + (SVL + lane * RS + 8 * jn) * 2);
            ldsm_x4_t(&vbl[4], sbase + (SVL + (32 + lane) * RS + 8 * jn) * 2);
            #pragma unroll
            for (int t = 0; t < 4; t++) {
                mma_bf16(o[jn], pah[t], vbh[2*t], vbh[2*t+1]);  // hi*hi
                mma_bf16(o[jn], pah[t], vbl[2*t], vbl[2*t+1]);  // hi*lo
                mma_bf16(o[jn], pal[t], vbh[2*t], vbh[2*t+1]);  // lo*hi
            }
        }
    }

    // ---- finalize + write ----
    float il0 = 1.0f / l0, il1 = 1.0f / l1;
    #pragma unroll
    for (int jn = 0; jn < 8; jn++) {
        int col = 8 * jn + 2 * (lane & 3);
        float2 v0 = make_float2(o[jn][0] * il0, o[jn][1] * il0);
        float2 v1 = make_float2(o[jn][2] * il1, o[jn][3] * il1);
        *(float2*)(merged + ((size_t)(b * SEQ + r_lo) * DIM) + h * HD + col) = v0;
        *(float2*)(merged + ((size_t)(b * SEQ + r_hi) * DIM) + h * HD + col) = v1;
        if (write_attn) {
            *(float2*)(attn_out + (((size_t)(b * NH + h) * SEQ + r_lo) * HD) + col) = v0;
            *(float2*)(attn_out + (((size_t)(b * NH + h) * SEQ + r_hi) * HD) + col) = v1;
        }
    }
}

// ---------------------------------------------------------------------------
extern "C" void kernel_launch(void* const* d_in, const int* in_sizes, int n_in,
                              void* d_out, int out_size)
{
    const float* q  = (const float*)d_in[0];
    const float* k  = (const float*)d_in[1];
    const float* v  = (const float*)d_in[2];
    const float* Wq = (const float*)d_in[3];
    const float* Wk = (const float*)d_in[4];
    const float* Wv = (const float*)d_in[5];
    const float* Wo = (const float*)d_in[6];
    const int* masked = (const int*)d_in[7];
    float* out = (float*)d_out;

    float* pM;
    __nv_bfloat16 *pQh, *pQl, *pKh, *pKl, *pVh, *pVl;
    cudaGetSymbolAddress((void**)&pM,  g_M);
    cudaGetSymbolAddress((void**)&pQh, g_Qh);
    cudaGetSymbolAddress((void**)&pQl, g_Ql);
    cudaGetSymbolAddress((void**)&pKh, g_Kh);
    cudaGetSymbolAddress((void**)&pKl, g_Kl);
    cudaGetSymbolAddress((void**)&pVh, g_Vh);
    cudaGetSymbolAddress((void**)&pVl, g_Vl);

    dim3 gGemm(DIM / GBN, NTOK / GBM);
    size_t gemm_smem = 2 * STAGE_FLOATS * sizeof(float);
    cudaFuncSetAttribute(gemm_tf32, cudaFuncAttributeMaxDynamicSharedMemorySize,
                         (int)gemm_smem);

    // Projections -> bf16 hi/lo planes (Q pre-scaled by 1/sqrt(hd))
    gemm_tf32<<<gGemm, 256, gemm_smem>>>(q, Wq, nullptr, pQh, pQl, 0.125f,
                                         NTOK, DIM, DIM);
    gemm_tf32<<<gGemm, 256, gemm_smem>>>(k, Wk, nullptr, pKh, pKl, 1.0f,
                                         NTOK, DIM, DIM);
    gemm_tf32<<<gGemm, 256, gemm_smem>>>(v, Wv, nullptr, pVh, pVl, 1.0f,
                                         NTOK, DIM, DIM);

    // Attention (bf16 tensor-core flash, fp32-accurate via 3-term split)
    int write_attn = (out_size >= (int)(2 * NELEM)) ? 1 : 0;
    float* attn_ptr = out + NELEM;
    size_t fl_smem = (size_t)SB_TOTAL * sizeof(__nv_bfloat16);
    cudaFuncSetAttribute(flash_bf16, cudaFuncAttributeMaxDynamicSharedMemorySize,
                         (int)fl_smem);
    dim3 gAttn(SEQ / 128, NH, BSZ);     // (16, 16, 2)
    flash_bf16<<<gAttn, 256, fl_smem>>>(pQh, pQl, pKh, pKl, pVh, pVl,
                                        pM, attn_ptr, write_attn, masked);

    // Output projection (fp32 out)
    gemm_tf32<<<gGemm, 256, gemm_smem>>>(pM, Wo, out, nullptr, nullptr, 1.0f,
                                         NTOK, DIM, DIM);
}

// round 4
// speedup vs baseline: 3.4254x; 1.1335x over previous
#include <cuda_runtime.h>
#include <cuda_bf16.h>
#include <math.h>

#define BSZ 2
#define SEQ 2048
#define DIM 1024
#define NH  16
#define HD  64
#define NTOK (BSZ*SEQ)            // 4096
#define NELEM ((size_t)NTOK*DIM)  // 4,194,304

// Scratch (allocation-free rule: __device__ globals)
__device__ float g_M[NELEM];               // merged attention output [B,S,H*HD]
__device__ __nv_bfloat16 g_Qh[NELEM], g_Ql[NELEM];
__device__ __nv_bfloat16 g_Kh[NELEM], g_Kl[NELEM];
__device__ __nv_bfloat16 g_Vh[NELEM], g_Vl[NELEM];

// ---------------------------------------------------------------------------
// small PTX helpers
// ---------------------------------------------------------------------------
__device__ __forceinline__ unsigned f2tf32(float f) {
    unsigned r;
    asm("cvt.rna.tf32.f32 %0, %1;" : "=r"(r) : "f"(f));
    return r;
}
__device__ __forceinline__ unsigned packbf2(float hi, float lo) {
    unsigned d;
    asm("cvt.rn.bf16x2.f32 %0, %1, %2;" : "=r"(d) : "f"(hi), "f"(lo));
    return d;
}
__device__ __forceinline__ void cp_async16(unsigned smem_addr, const void* gptr) {
    asm volatile("cp.async.cg.shared.global [%0], [%1], 16;\n"
                 :: "r"(smem_addr), "l"(gptr));
}
__device__ __forceinline__ void cp_commit() {
    asm volatile("cp.async.commit_group;\n");
}
template <int N>
__device__ __forceinline__ void cp_wait() {
    asm volatile("cp.async.wait_group %0;\n" :: "n"(N));
}
__device__ __forceinline__ void ldsm_x4(unsigned* r, unsigned addr) {
    asm volatile("ldmatrix.sync.aligned.m8n8.x4.shared.b16 {%0,%1,%2,%3}, [%4];"
                 : "=r"(r[0]), "=r"(r[1]), "=r"(r[2]), "=r"(r[3]) : "r"(addr));
}
__device__ __forceinline__ void ldsm_x4_t(unsigned* r, unsigned addr) {
    asm volatile("ldmatrix.sync.aligned.m8n8.x4.trans.shared.b16 {%0,%1,%2,%3}, [%4];"
                 : "=r"(r[0]), "=r"(r[1]), "=r"(r[2]), "=r"(r[3]) : "r"(addr));
}
__device__ __forceinline__ void mma_bf16(float* c, const unsigned* a,
                                         unsigned b0, unsigned b1) {
    asm volatile(
        "mma.sync.aligned.m16n8k16.row.col.f32.bf16.bf16.f32 "
        "{%0,%1,%2,%3},{%4,%5,%6,%7},{%8,%9},{%0,%1,%2,%3};"
        : "+f"(c[0]), "+f"(c[1]), "+f"(c[2]), "+f"(c[3])
        : "r"(a[0]), "r"(a[1]), "r"(a[2]), "r"(a[3]), "r"(b0), "r"(b1));
}

// ---------------------------------------------------------------------------
// TF32 tensor-core GEMM (unchanged mainloop); epilogue optionally emits
// bf16 hi/lo planes (for Q/K/V) instead of fp32.
// ---------------------------------------------------------------------------
#define GBM 128
#define GBN 128
#define GBK 32
#define ASTRIDE 36
#define BSTRIDE 136
#define STAGE_FLOATS (GBM*ASTRIDE + GBK*BSTRIDE)

__global__ void __launch_bounds__(256, 2)
gemm_tf32(const float* __restrict__ A, const float* __restrict__ B,
          float* __restrict__ Cf,
          __nv_bfloat16* __restrict__ Ch, __nv_bfloat16* __restrict__ Cl,
          float scale, int M, int N, int K)
{
    extern __shared__ float sm[];
    const int tid  = threadIdx.x;
    const int lane = tid & 31;
    const int warp = tid >> 5;
    const int wm   = warp >> 2;
    const int wn   = warp & 3;

    const int bRow = blockIdx.y;
    const int bCol = blockIdx.x;

    const float* Ab = A + (size_t)bRow * GBM * K;
    const float* Bb = B + (size_t)bCol * GBN;

    unsigned smem_base;
    asm("{ .reg .u64 t; cvta.to.shared.u64 t, %1; cvt.u32.u64 %0, t; }"
        : "=r"(smem_base) : "l"(sm));

    const int aRowL = tid >> 3;
    const int aColL = (tid & 7) * 4;
    const int bRowL = tid >> 5;
    const int bColL = (tid & 31) * 4;

    float c[4][4][4];
    #pragma unroll
    for (int mt = 0; mt < 4; mt++)
        #pragma unroll
        for (int nt = 0; nt < 4; nt++)
            #pragma unroll
            for (int e = 0; e < 4; e++) c[mt][nt][e] = 0.0f;

    const int niter = K / GBK;

    auto load_stage = [&](int iter, int buf) {
        const int k0 = iter * GBK;
        unsigned aBase = smem_base + (unsigned)(buf * STAGE_FLOATS) * 4u;
        unsigned bBase = aBase + GBM * ASTRIDE * 4u;
        #pragma unroll
        for (int it = 0; it < 4; it++) {
            int r = aRowL + it * 32;
            cp_async16(aBase + (r * ASTRIDE + aColL) * 4u,
                       Ab + (size_t)r * K + k0 + aColL);
        }
        #pragma unroll
        for (int it = 0; it < 4; it++) {
            int r = bRowL + it * 8;
            cp_async16(bBase + (r * BSTRIDE + bColL) * 4u,
                       Bb + (size_t)(k0 + r) * N + bColL);
        }
    };

    load_stage(0, 0); cp_commit();
    load_stage(1, 1); cp_commit();

    const int g  = lane >> 2;
    const int tg = lane & 3;

    for (int i = 0; i < niter; i++) {
        cp_wait<1>();
        __syncthreads();

        const int buf = i & 1;
        const float* As = sm + buf * STAGE_FLOATS;
        const float* Bs = As + GBM * ASTRIDE;

        #pragma unroll
        for (int kk = 0; kk < GBK / 8; kk++) {
            unsigned af[4][4], bf[4][2];
            const int c0 = kk * 8 + tg;
            #pragma unroll
            for (int mt = 0; mt < 4; mt++) {
                int r0 = wm * 64 + mt * 16 + g;
                af[mt][0] = f2tf32(As[r0       * ASTRIDE + c0]);
                af[mt][1] = f2tf32(As[(r0 + 8) * ASTRIDE + c0]);
                af[mt][2] = f2tf32(As[r0       * ASTRIDE + c0 + 4]);
                af[mt][3] = f2tf32(As[(r0 + 8) * ASTRIDE + c0 + 4]);
            }
            #pragma unroll
            for (int nt = 0; nt < 4; nt++) {
                int col = wn * 32 + nt * 8 + g;
                bf[nt][0] = f2tf32(Bs[c0       * BSTRIDE + col]);
                bf[nt][1] = f2tf32(Bs[(c0 + 4) * BSTRIDE + col]);
            }
            #pragma unroll
            for (int mt = 0; mt < 4; mt++)
                #pragma unroll
                for (int nt = 0; nt < 4; nt++) {
                    asm volatile(
                        "mma.sync.aligned.m16n8k8.row.col.f32.tf32.tf32.f32 "
                        "{%0,%1,%2,%3},{%4,%5,%6,%7},{%8,%9},{%0,%1,%2,%3};\n"
                        : "+f"(c[mt][nt][0]), "+f"(c[mt][nt][1]),
                          "+f"(c[mt][nt][2]), "+f"(c[mt][nt][3])
                        : "r"(af[mt][0]), "r"(af[mt][1]),
                          "r"(af[mt][2]), "r"(af[mt][3]),
                          "r"(bf[nt][0]), "r"(bf[nt][1]));
                }
        }
        __syncthreads();
        if (i + 2 < niter) load_stage(i + 2, buf);
        cp_commit();
    }

    // Epilogue
    if (Ch) {
        #pragma unroll
        for (int mt = 0; mt < 4; mt++) {
            int r0 = bRow * GBM + wm * 64 + mt * 16 + g;
            #pragma unroll
            for (int nt = 0; nt < 4; nt++) {
                int col = bCol * GBN + wn * 32 + nt * 8 + 2 * tg;
                #pragma unroll
                for (int half = 0; half < 2; half++) {
                    size_t off = (size_t)(r0 + 8 * half) * N + col;
                    float y0 = c[mt][nt][2 * half + 0] * scale;
                    float y1 = c[mt][nt][2 * half + 1] * scale;
                    unsigned hi = packbf2(y1, y0);
                    float h0 = __uint_as_float(hi << 16);
                    float h1 = __uint_as_float(hi & 0xffff0000u);
                    unsigned lo = packbf2(y1 - h1, y0 - h0);
                    *(unsigned*)((__nv_bfloat16*)Ch + off) = hi;
                    *(unsigned*)((__nv_bfloat16*)Cl + off) = lo;
                }
            }
        }
    } else {
        float* Cb = Cf + (size_t)bRow * GBM * N + bCol * GBN;
        #pragma unroll
        for (int mt = 0; mt < 4; mt++) {
            int r0 = wm * 64 + mt * 16 + g;
            #pragma unroll
            for (int nt = 0; nt < 4; nt++) {
                int col = wn * 32 + nt * 8 + 2 * tg;
                *(float2*)(Cb + (size_t)r0 * N + col) =
                    make_float2(c[mt][nt][0], c[mt][nt][1]);
                *(float2*)(Cb + (size_t)(r0 + 8) * N + col) =
                    make_float2(c[mt][nt][2], c[mt][nt][3]);
            }
        }
    }
}

// ---------------------------------------------------------------------------
// Flash attention, bf16 tensor cores, 3-term hi/lo split, cp.async
// double-buffered K/V tiles. Q smem region is reused as KV stage 1 after the
// Q fragments are hoisted to registers -> smem stays 73.7KB.
// ---------------------------------------------------------------------------
#define RS 72                          // smem row stride (bf16), conflict-free
#define KVSTAGE (4*64*RS)              // one KV stage: KH,KL,VH,VL  (18432 bf16)
// region A: [0, 2*128*RS) = Q planes, later KV stage 1 (2*128*RS == KVSTAGE)
// region B: [2*128*RS, 4*128*RS) = KV stage 0
#define SQH 0
#define SQL (128*RS)
#define SB_TOTAL (2*KVSTAGE)           // 36864 bf16 = 73728 B
// offsets within a KV stage:
#define OKH 0
#define OKL (64*RS)
#define OVH (128*RS)
#define OVL (192*RS)

__global__ void __launch_bounds__(256, 1)
flash_bf16(const __nv_bfloat16* __restrict__ Qh, const __nv_bfloat16* __restrict__ Ql,
           const __nv_bfloat16* __restrict__ Kh, const __nv_bfloat16* __restrict__ Kl,
           const __nv_bfloat16* __restrict__ Vh, const __nv_bfloat16* __restrict__ Vl,
           float* __restrict__ merged, float* __restrict__ attn_out,
           int write_attn, const int* __restrict__ maskedp)
{
    extern __shared__ __nv_bfloat16 sb[];
    const int qt  = gridDim.x - 1 - blockIdx.x;   // heavy blocks first
    const int h   = blockIdx.y;
    const int b   = blockIdx.z;
    const int tid = threadIdx.x;
    const int lane = tid & 31;
    const int w   = tid >> 5;
    const int q0  = qt * 128;
    const int masked = maskedp[0];

    unsigned sbase;
    asm("{ .reg .u64 t; cvta.to.shared.u64 t, %1; cvt.u32.u64 %0, t; }"
        : "=r"(sbase) : "l"(sb));

    const int ktmax = masked ? (2 * qt + 1) : (SEQ / 64 - 1);

    // stage bases (bf16 offsets): tile kt lives in stage (kt & 1)
    //   stage 0 -> region B (KVSTAGE), stage 1 -> region A (0)
    auto stage_off = [](int kt) -> unsigned { return (kt & 1) ? 0u : (unsigned)KVSTAGE; };

    // cooperative cp.async prefetch of K/V tile t (8 x 16B per thread)
    auto prefetch = [&](int t) {
        if (t <= ktmax) {
            unsigned so = stage_off(t);
            int r  = tid >> 3;               // 0..31 (+32)
            int c8 = (tid & 7) << 3;
            #pragma unroll
            for (int half = 0; half < 2; half++) {
                int rr = r + 32 * half;
                size_t gidx = ((size_t)(b * SEQ + t * 64 + rr) * DIM) + h * HD + c8;
                unsigned sa = sbase + (so + rr * RS + c8) * 2;
                cp_async16(sa + OKH * 2, Kh + gidx);
                cp_async16(sa + OKL * 2, Kl + gidx);
                cp_async16(sa + OVH * 2, Vh + gidx);
                cp_async16(sa + OVL * 2, Vl + gidx);
            }
        }
        cp_commit();   // exactly one group per call (possibly empty)
    };

    // kick off tile 0 into region B, then load Q into region A
    prefetch(0);
    for (int i = tid; i < 1024; i += 256) {
        int r = i >> 3, c8 = (i & 7) << 3;
        size_t gidx = ((size_t)(b * SEQ + q0 + r) * DIM) + h * HD + c8;
        *(uint4*)(sb + SQH + r * RS + c8) = *(const uint4*)(Qh + gidx);
        *(uint4*)(sb + SQL + r * RS + c8) = *(const uint4*)(Ql + gidx);
    }
    __syncthreads();

    // hoist Q A-frags: [plane][dstep][4regs]
    unsigned qf[2][4][4];
    {
        int row  = 16 * w + (lane & 15);
        int coct = (lane >> 4) << 3;
        #pragma unroll
        for (int p = 0; p < 2; p++)
            #pragma unroll
            for (int d = 0; d < 4; d++) {
                unsigned addr = sbase +
                    ((p ? SQL : SQH) + row * RS + d * 16 + coct) * 2;
                ldsm_x4(qf[p][d], addr);
            }
    }
    __syncthreads();   // region A free -> becomes KV stage 1
    prefetch(1);       // tile 1 into region A

    float o[8][4];
    #pragma unroll
    for (int j = 0; j < 8; j++)
        #pragma unroll
        for (int e = 0; e < 4; e++) o[j][e] = 0.0f;
    float m0 = -1e30f, m1 = -1e30f, l0 = 0.0f, l1 = 0.0f;

    const int r_lo = q0 + 16 * w + (lane >> 2);
    const int r_hi = r_lo + 8;

    for (int kt = 0; kt <= ktmax; kt++) {
        cp_wait<1>();
        __syncthreads();

        const unsigned so = stage_off(kt);
        const int k0 = kt * 64;
        const bool active = !(masked && k0 > q0 + 16 * w + 15);

        if (active) {
            // ---- QK^T ----
            float s[8][4];
            #pragma unroll
            for (int j = 0; j < 8; j++)
                #pragma unroll
                for (int e = 0; e < 4; e++) s[j][e] = 0.0f;

            #pragma unroll
            for (int j = 0; j < 8; j++) {
                unsigned kbh[8], kbl[8];
                int krow = 8 * j + (lane & 7);
                int dct  = (lane >> 3) << 3;
                ldsm_x4(&kbh[0], sbase + (so + OKH + krow * RS + dct) * 2);
                ldsm_x4(&kbh[4], sbase + (so + OKH + krow * RS + 32 + dct) * 2);
                ldsm_x4(&kbl[0], sbase + (so + OKL + krow * RS + dct) * 2);
                ldsm_x4(&kbl[4], sbase + (so + OKL + krow * RS + 32 + dct) * 2);
                #pragma unroll
                for (int d = 0; d < 4; d++) {
                    mma_bf16(s[j], qf[0][d], kbh[2*d], kbh[2*d+1]);
                    mma_bf16(s[j], qf[0][d], kbl[2*d], kbl[2*d+1]);
                    mma_bf16(s[j], qf[1][d], kbh[2*d], kbh[2*d+1]);
                }
            }

            // ---- causal mask (diagonal band) ----
            if (masked && k0 + 63 > r_lo) {
                #pragma unroll
                for (int j = 0; j < 8; j++) {
                    int cc = k0 + 8 * j + 2 * (lane & 3);
                    if (cc     > r_lo) s[j][0] = -1e30f;
                    if (cc + 1 > r_lo) s[j][1] = -1e30f;
                    if (cc     > r_hi) s[j][2] = -1e30f;
                    if (cc + 1 > r_hi) s[j][3] = -1e30f;
                }
            }

            // ---- online softmax ----
            float mt0 = -1e30f, mt1 = -1e30f;
            #pragma unroll
            for (int j = 0; j < 8; j++) {
                mt0 = fmaxf(mt0, fmaxf(s[j][0], s[j][1]));
                mt1 = fmaxf(mt1, fmaxf(s[j][2], s[j][3]));
            }
            mt0 = fmaxf(mt0, __shfl_xor_sync(0xffffffffu, mt0, 1));
            mt0 = fmaxf(mt0, __shfl_xor_sync(0xffffffffu, mt0, 2));
            mt1 = fmaxf(mt1, __shfl_xor_sync(0xffffffffu, mt1, 1));
            mt1 = fmaxf(mt1, __shfl_xor_sync(0xffffffffu, mt1, 2));
            float mn0 = fmaxf(m0, mt0), mn1 = fmaxf(m1, mt1);
            float a0 = __expf(m0 - mn0), a1 = __expf(m1 - mn1);
            m0 = mn0; m1 = mn1;

            float rs0 = 0.0f, rs1 = 0.0f;
            unsigned pah[4][4], pal[4][4];
            #pragma unroll
            for (int j = 0; j < 8; j++) {
                float p0 = __expf(s[j][0] - mn0);
                float p1 = __expf(s[j][1] - mn0);
                float p2 = __expf(s[j][2] - mn1);
                float p3 = __expf(s[j][3] - mn1);
                rs0 += p0 + p1; rs1 += p2 + p3;
                unsigned h01 = packbf2(p1, p0);
                unsigned h23 = packbf2(p3, p2);
                float q0f = __uint_as_float(h01 << 16);
                float q1f = __uint_as_float(h01 & 0xffff0000u);
                float q2f = __uint_as_float(h23 << 16);
                float q3f = __uint_as_float(h23 & 0xffff0000u);
                unsigned lo01 = packbf2(p1 - q1f, p0 - q0f);
                unsigned lo23 = packbf2(p3 - q3f, p2 - q2f);
                int t = j >> 1, half = j & 1;
                pah[t][2 * half + 0] = h01;
                pah[t][2 * half + 1] = h23;
                pal[t][2 * half + 0] = lo01;
                pal[t][2 * half + 1] = lo23;
            }
            rs0 += __shfl_xor_sync(0xffffffffu, rs0, 1);
            rs0 += __shfl_xor_sync(0xffffffffu, rs0, 2);
            rs1 += __shfl_xor_sync(0xffffffffu, rs1, 1);
            rs1 += __shfl_xor_sync(0xffffffffu, rs1, 2);
            l0 = l0 * a0 + rs0;
            l1 = l1 * a1 + rs1;
            #pragma unroll
            for (int j = 0; j < 8; j++) {
                o[j][0] *= a0; o[j][1] *= a0;
                o[j][2] *= a1; o[j][3] *= a1;
            }

            // ---- PV ----
            #pragma unroll
            for (int jn = 0; jn < 8; jn++) {
                unsigned vbh[8], vbl[8];
                ldsm_x4_t(&vbh[0], sbase + (so + OVH + lane * RS + 8 * jn) * 2);
                ldsm_x4_t(&vbh[4], sbase + (so + OVH + (32 + lane) * RS + 8 * jn) * 2);
                ldsm_x4_t(&vbl[0], sbase + (so + OVL + lane * RS + 8 * jn) * 2);
                ldsm_x4_t(&vbl[4], sbase + (so + OVL + (32 + lane) * RS + 8 * jn) * 2);
                #pragma unroll
                for (int t = 0; t < 4; t++) {
                    mma_bf16(o[jn], pah[t], vbh[2*t], vbh[2*t+1]);
                    mma_bf16(o[jn], pah[t], vbl[2*t], vbl[2*t+1]);
                    mma_bf16(o[jn], pal[t], vbh[2*t], vbh[2*t+1]);
                }
            }
        }

        __syncthreads();      // all warps done reading stage(kt)
        prefetch(kt + 2);     // refill the stage we just consumed
    }

    // ---- finalize + write ----
    float il0 = 1.0f / l0, il1 = 1.0f / l1;
    #pragma unroll
    for (int jn = 0; jn < 8; jn++) {
        int col = 8 * jn + 2 * (lane & 3);
        float2 v0 = make_float2(o[jn][0] * il0, o[jn][1] * il0);
        float2 v1 = make_float2(o[jn][2] * il1, o[jn][3] * il1);
        *(float2*)(merged + ((size_t)(b * SEQ + r_lo) * DIM) + h * HD + col) = v0;
        *(float2*)(merged + ((size_t)(b * SEQ + r_hi) * DIM) + h * HD + col) = v1;
        if (write_attn) {
            *(float2*)(attn_out + (((size_t)(b * NH + h) * SEQ + r_lo) * HD) + col) = v0;
            *(float2*)(attn_out + (((size_t)(b * NH + h) * SEQ + r_hi) * HD) + col) = v1;
        }
    }
}

// ---------------------------------------------------------------------------
extern "C" void kernel_launch(void* const* d_in, const int* in_sizes, int n_in,
                              void* d_out, int out_size)
{
    const float* q  = (const float*)d_in[0];
    const float* k  = (const float*)d_in[1];
    const float* v  = (const float*)d_in[2];
    const float* Wq = (const float*)d_in[3];
    const float* Wk = (const float*)d_in[4];
    const float* Wv = (const float*)d_in[5];
    const float* Wo = (const float*)d_in[6];
    const int* masked = (const int*)d_in[7];
    float* out = (float*)d_out;

    float* pM;
    __nv_bfloat16 *pQh, *pQl, *pKh, *pKl, *pVh, *pVl;
    cudaGetSymbolAddress((void**)&pM,  g_M);
    cudaGetSymbolAddress((void**)&pQh, g_Qh);
    cudaGetSymbolAddress((void**)&pQl, g_Ql);
    cudaGetSymbolAddress((void**)&pKh, g_Kh);
    cudaGetSymbolAddress((void**)&pKl, g_Kl);
    cudaGetSymbolAddress((void**)&pVh, g_Vh);
    cudaGetSymbolAddress((void**)&pVl, g_Vl);

    dim3 gGemm(DIM / GBN, NTOK / GBM);
    size_t gemm_smem = 2 * STAGE_FLOATS * sizeof(float);
    cudaFuncSetAttribute(gemm_tf32, cudaFuncAttributeMaxDynamicSharedMemorySize,
                         (int)gemm_smem);

    // Projections -> bf16 hi/lo planes (Q pre-scaled by 1/sqrt(hd))
    gemm_tf32<<<gGemm, 256, gemm_smem>>>(q, Wq, nullptr, pQh, pQl, 0.125f,
                                         NTOK, DIM, DIM);
    gemm_tf32<<<gGemm, 256, gemm_smem>>>(k, Wk, nullptr, pKh, pKl, 1.0f,
                                         NTOK, DIM, DIM);
    gemm_tf32<<<gGemm, 256, gemm_smem>>>(v, Wv, nullptr, pVh, pVl, 1.0f,
                                         NTOK, DIM, DIM);

    // Attention
    int write_attn = (out_size >= (int)(2 * NELEM)) ? 1 : 0;
    float* attn_ptr = out + NELEM;
    size_t fl_smem = (size_t)SB_TOTAL * sizeof(__nv_bfloat16);
    cudaFuncSetAttribute(flash_bf16, cudaFuncAttributeMaxDynamicSharedMemorySize,
                         (int)fl_smem);
    dim3 gAttn(SEQ / 128, NH, BSZ);     // (16, 16, 2)
    flash_bf16<<<gAttn, 256, fl_smem>>>(pQh, pQl, pKh, pKl, pVh, pVl,
                                        pM, attn_ptr, write_attn, masked);

    // Output projection (fp32 out)
    gemm_tf32<<<gGemm, 256, gemm_smem>>>(pM, Wo, out, nullptr, nullptr, 1.0f,
                                         NTOK, DIM, DIM);
}